// round 14
// baseline (speedup 1.0000x reference)
#include <cuda_runtime.h>
#include <cuda_bf16.h>
#include <math.h>
#include <stdint.h>

#define NB 16
#define NS 16384
#define NC 64
#define NM 16
#define NPSP 500
#define NPFR 200
#define NED 8
#define NCH 128         // DFT chunks over s (128 s each) — matches producer blocks

typedef unsigned long long ull;

__device__ __forceinline__ ull f2pack(float lo, float hi) {
    ull r; asm("mov.b64 %0, {%1,%2};" : "=l"(r) : "f"(lo), "f"(hi)); return r;
}
__device__ __forceinline__ void f2unpack(ull v, float& lo, float& hi) {
    asm("mov.b64 {%0,%1}, %2;" : "=f"(lo), "=f"(hi) : "l"(v));
}
__device__ __forceinline__ ull f2fma(ull a, ull b, ull c) {
    ull d; asm("fma.rn.f32x2 %0, %1, %2, %3;" : "=l"(d) : "l"(a), "l"(b), "l"(c)); return d;
}

// -------- scratch (static device globals; no runtime allocation) -----------
__device__ float g_h[NB * NS * NC];                 // [b][s][c]  64 MB
__device__ float g_tw[NS * 32];                     // per s: cos[16], sin[16]
__device__ int   g_idx[NB * NS];                    // spatial engram idx
__device__ float g_xpart[NB * NCH * NC * 32];       // DFT partials (16.8 MB)
__device__ float g_epart[NB * 64 * NED];            // embedding partial sums
__device__ float g_cR[NB * NC * NM];                // combined mode coef (pre-scaled)
__device__ float g_cI[NB * NC * NM];
__device__ float g_w0[NB];                          // gate weight for sp branch

// ---------------------------------------------------------------------------
// fp32 twiddles with exact integer phase reduction
__global__ void k_twiddle() {
    int s = blockIdx.x * 256 + threadIdx.x;
    if (s >= NS) return;
#pragma unroll
    for (int k = 0; k < 16; k++) {
        int r = (k * s) & (NS - 1);
        float a = (float)r * (2.0f * 3.14159265358979323846f / (float)NS);
        float sv, cv; sincosf(a, &sv, &cv);
        g_tw[s * 32 + k]      = cv;
        g_tw[s * 32 + 16 + k] = sv;
    }
}

// ---- shared helper: two-pass (cos, sin) cross-group reduction + xpart write.
// Each thread holds aC[8], aS[8] (k-pairs) for channel c, s-subgroup sg.
// stw16 is a 16KB (4096-float) buffer free for reuse.
__device__ __forceinline__ void dft_reduce_write(float* stw16, ull* aC, ull* aS,
                                                 int t, int c, int sg,
                                                 float* xp) {
#pragma unroll
    for (int j = 0; j < 8; j++) {
        float lo, hi;
        f2unpack(aC[j], lo, hi);
        stw16[((2*j)   * 64 + c) * 4 + sg] = lo;
        stw16[((2*j+1) * 64 + c) * 4 + sg] = hi;
    }
    __syncthreads();
#pragma unroll
    for (int it = 0; it < 4; it++) {
        int p = t + it * 256;            // p = k*64 + c
        int k = p >> 6, cc = p & 63;
        const float* r = stw16 + p * 4;
        xp[cc * 32 + k] = ((r[0] + r[1]) + r[2]) + r[3];
    }
    __syncthreads();
#pragma unroll
    for (int j = 0; j < 8; j++) {
        float lo, hi;
        f2unpack(aS[j], lo, hi);
        stw16[((2*j)   * 64 + c) * 4 + sg] = lo;
        stw16[((2*j+1) * 64 + c) * 4 + sg] = hi;
    }
    __syncthreads();
#pragma unroll
    for (int it = 0; it < 4; it++) {
        int p = t + it * 256;
        int k = p >> 6, cc = p & 63;
        const float* r = stw16 + p * 4;
        xp[cc * 32 + 16 + k] = ((r[0] + r[1]) + r[2]) + r[3];
    }
}

// lifting fused with layer-0 DFT partials. Block = 128 s x all channels.
__global__ void __launch_bounds__(256, 2) k_lift(const float* __restrict__ x,
                       const float* __restrict__ W,
                       const float* __restrict__ bias) {
    __shared__ float stw[128 * 32];      // tw slice (16KB), reused for reduction
    __shared__ float lw[3 * NC], lb[NC];
    int b = blockIdx.y, chunk = blockIdx.x, t = threadIdx.x;
    {
        const float4* gtw = (const float4*)(g_tw + chunk * 128 * 32);
        float4* stw4 = (float4*)stw;
#pragma unroll
        for (int j = 0; j < 4; j++) stw4[t + j * 256] = gtw[t + j * 256];
    }
    if (t < 192) lw[t] = W[t];
    if (t < NC)  lb[t] = bias[t];
    __syncthreads();
    int c = t & 63, sg = t >> 6;
    ull aC[8], aS[8];
#pragma unroll
    for (int j = 0; j < 8; j++) { aC[j] = 0ull; aS[j] = 0ull; }
    const float* xb = x + b * 3 * NS;
    float W0 = lw[c], W1 = lw[64 + c], W2 = lw[128 + c], B0 = lb[c];
    for (int i = 0; i < 32; i++) {
        int l = i * 4 + sg;
        int s = chunk * 128 + l;
        float x0 = xb[s], x1 = xb[NS + s], x2 = xb[2 * NS + s];
        float hv = B0 + x0 * W0 + x1 * W1 + x2 * W2;
        g_h[(b * NS + s) * NC + c] = hv;
        const ulonglong2* tw2 = (const ulonglong2*)(stw + l * 32);
        ull d = f2pack(hv, hv);
#pragma unroll
        for (int q = 0; q < 4; q++) {
            ulonglong2 tc = tw2[q];
            aC[2*q]   = f2fma(d, tc.x, aC[2*q]);
            aC[2*q+1] = f2fma(d, tc.y, aC[2*q+1]);
        }
#pragma unroll
        for (int q = 0; q < 4; q++) {
            ulonglong2 ts = tw2[4 + q];
            aS[2*q]   = f2fma(d, ts.x, aS[2*q]);
            aS[2*q+1] = f2fma(d, ts.y, aS[2*q+1]);
        }
    }
    __syncthreads();
    float* xp = g_xpart + (size_t)(b * NCH + chunk) * NC * 32;
    dft_reduce_write(stw, aC, aS, t, c, sg, xp);
}

// fused: channel sums (with 4-halo in smem) -> window hash -> idx + emb partials
__global__ void k_scidx(const float* __restrict__ sp_emb, int layer) {
    __shared__ float ssc[260];
    __shared__ float wred[8 * NED];
    int b = blockIdx.y, t = threadIdx.x;
    int base = blockIdx.x * 256;
    for (int j = t; j < 260; j += 256) {
        int s = base + j - 2;
        s = s < 0 ? 0 : (s > NS - 1 ? NS - 1 : s);
        const float4* hp = (const float4*)(g_h + (b * NS + s) * NC);
        float acc = 0.0f;
#pragma unroll
        for (int q = 0; q < 16; q++) {
            float4 v = hp[q];
            acc += v.x; acc += v.y; acc += v.z; acc += v.w;
        }
        ssc[j] = acc;
    }
    __syncthreads();
    int s = base + t;
    float w = ((ssc[t] + ssc[t + 1]) + ssc[t + 2]) + ssc[t + 3];
    int iv = (int)(w * 31.0f);
    iv = ((iv % NPSP) + NPSP) % NPSP;
    g_idx[b * NS + s] = iv;
    const float* em = sp_emb + (layer * NPSP + iv) * NED;
    float ev[NED];
#pragma unroll
    for (int e = 0; e < NED; e++) ev[e] = em[e];
#pragma unroll
    for (int off = 16; off > 0; off >>= 1) {
#pragma unroll
        for (int e = 0; e < NED; e++)
            ev[e] += __shfl_xor_sync(0xffffffffu, ev[e], off);
    }
    int wid = t >> 5, lid = t & 31;
    if (lid == 0) {
#pragma unroll
        for (int e = 0; e < NED; e++) wred[wid * NED + e] = ev[e];
    }
    __syncthreads();
    if (t < NED) {
        float acc = 0.f;
#pragma unroll
        for (int ww = 0; ww < 8; ww++) acc += wred[ww * NED + t];
        g_epart[(b * 64 + blockIdx.x) * NED + t] = acc;
    }
}

// per-b small math: X reduce, mags+fr hash, mh einsum, fr proj, gate MLP, coef combine
__global__ void k_small(const float* __restrict__ sp_W, const float* __restrict__ sp_b,
                        const float* __restrict__ fr_emb, const float* __restrict__ fr_W,
                        const float* __restrict__ fr_b,
                        const float* __restrict__ gW1, const float* __restrict__ gb1,
                        const float* __restrict__ gW2, const float* __restrict__ gb2,
                        const float* __restrict__ Wr, const float* __restrict__ Wi,
                        int layer) {
    __shared__ float sXR[1024], sXI[1024], sOR[1024], sOI[1024], sPR[1024];
    __shared__ float sMag[16], sEmb[8], sEm[8], sG[192], sH1[64], sW[3];
    __shared__ int sFidx;
    int b = blockIdx.x, t = threadIdx.x;
    const float invS = 1.0f / (float)NS;

    for (int it = 0; it < 4; it++) {
        int p = t + it * 256;            // p = c*16 + k
        int c = p >> 4, k = p & 15;
        float sc_ = 0.f, ss = 0.f;
        const float* src0 = g_xpart + (size_t)(b * NCH * NC + c) * 32 + k;
#pragma unroll 8
        for (int ch = 0; ch < NCH; ch++) {
            const float* src = src0 + (size_t)ch * NC * 32;
            sc_ += src[0]; ss += src[16];
        }
        sXR[p] = sc_; sXI[p] = -ss;      // rfft: Im = -sum x*sin
    }
    __syncthreads();

    if (t < 16) {
        float acc = 0.f;
        for (int c = 0; c < NC; c++) {
            float xr = sXR[c * 16 + t], xi = sXI[c * 16 + t];
            acc += sqrtf(xr * xr + xi * xi);
        }
        sMag[t] = acc * (1.0f / 64.0f);
    }
    __syncthreads();
    if (t == 0) {
        int s = 0;
        for (int m = 0; m < 16; m++) s += (int)(sMag[m] * 1000.0f);
        sFidx = ((s % NPFR) + NPFR) % NPFR;
    }
    __syncthreads();
    if (t < 8) sEmb[t] = fr_emb[(layer * NPFR + sFidx) * NED + t];

    for (int it = 0; it < 4; it++) {
        int p = t + it * 256;
        int oc = p >> 4, m = p & 15;
        int hh = oc >> 4, o = oc & 15;
        float aR = 0.f, aI = 0.f;
#pragma unroll 4
        for (int i = 0; i < 16; i++) {
            float xr = sXR[(hh * 16 + i) * 16 + m];
            float xi = sXI[(hh * 16 + i) * 16 + m];
            int wi_ = (((layer * 4 + hh) * 16 + i) * 16 + o) * 16 + m;
            float wr = Wr[wi_], wim = Wi[wi_];
            aR += xr * wr - xi * wim;
            aI += xr * wim + xi * wr;
        }
        sOR[p] = aR; sOI[p] = aI;
    }
    __syncthreads();

    for (int it = 0; it < 4; it++) {
        int p = t + it * 256;
        int c = p >> 4, m = p & 15;
        float acc = fr_b[layer * 1024 + c * 16 + m];
#pragma unroll
        for (int e = 0; e < NED; e++)
            acc += sEmb[e] * fr_W[(layer * NED + e) * 1024 + c * 16 + m];
        sPR[p] = acc;
    }

    if (t < 8) {
        float acc = 0.f;
#pragma unroll 8
        for (int blk = 0; blk < 64; blk++) acc += g_epart[(b * 64 + blk) * NED + t];
        sEm[t] = acc * invS;
    }
    __syncthreads();

    if (t < 64) {
        float sm = sp_b[layer * NC + t];
#pragma unroll
        for (int e = 0; e < NED; e++) sm += sEm[e] * sp_W[(layer * NED + e) * NC + t];
        sG[t]       = sm;
        sG[64 + t]  = sOR[t * 16] * invS;
        sG[128 + t] = sPR[t * 16] * invS;
    }
    __syncthreads();
    if (t < 64) {
        float acc = gb1[layer * 64 + t];
#pragma unroll 8
        for (int i = 0; i < 192; i++) acc += sG[i] * gW1[(layer * 192 + i) * 64 + t];
        sH1[t] = fmaxf(acc, 0.0f);
    }
    __syncthreads();
    if (t < 3) {
        float acc = gb2[layer * 3 + t];
        for (int i = 0; i < 64; i++) acc += sH1[i] * gW2[(layer * 64 + i) * 3 + t];
        sW[t] = acc;
    }
    __syncthreads();
    if (t == 0) {
        float mx = fmaxf(sW[0], fmaxf(sW[1], sW[2]));
        float e0 = expf(sW[0] - mx), e1 = expf(sW[1] - mx), e2 = expf(sW[2] - mx);
        float inv = 1.0f / (e0 + e1 + e2);
        sW[0] = e0 * inv; sW[1] = e1 * inv; sW[2] = e2 * inv;
        g_w0[b] = sW[0];
    }
    __syncthreads();

    float w1 = sW[1], w2 = sW[2];
    for (int it = 0; it < 4; it++) {
        int p = t + it * 256;
        int k = p & 15;
        float scale = (k == 0) ? invS : 2.0f * invS;
        g_cR[b * 1024 + p] = (w1 * sOR[p] + w2 * sPR[p]) * scale;
        g_cI[b * 1024 + p] = (w1 * sOI[p]) * scale;
    }
}

// fused synthesis + NEXT layer's DFT partial accumulation.
// h = gelu( w0*sp + sum_k (cR cos - cI sin) ); if do_dft, accumulate h*tw partials.
__global__ void __launch_bounds__(256, 2) k_synth(const float* __restrict__ sp_emb,
                        const float* __restrict__ sp_W,
                        const float* __restrict__ sp_b, int layer, int do_dft) {
    __shared__ float stw[128 * 32];      // tw slice (16KB), reused for reduction
    __shared__ float sw[NED * NC], sb[NC];
    int b = blockIdx.y, t = threadIdx.x;
    {
        const float4* gtw = (const float4*)(g_tw + blockIdx.x * 128 * 32);
        float4* stw4 = (float4*)stw;
#pragma unroll
        for (int j = 0; j < 4; j++) stw4[t + j * 256] = gtw[t + j * 256];
    }
    for (int p = t; p < NED * NC; p += 256) sw[p] = sp_W[layer * NED * NC + p];
    if (t < NC) sb[t] = sp_b[layer * NC + t];
    __syncthreads();
    int c = t & 63, sg = t >> 6;
    ull cRp[8], cIp[8];
    {
        const ull* crp = (const ull*)(g_cR + (b * NC + c) * NM);
        const ull* cip = (const ull*)(g_cI + (b * NC + c) * NM);
#pragma unroll
        for (int j = 0; j < 8; j++) { cRp[j] = crp[j]; cIp[j] = cip[j]; }
    }
    ull aC[8], aS[8];
#pragma unroll
    for (int j = 0; j < 8; j++) { aC[j] = 0ull; aS[j] = 0ull; }
    float w0 = g_w0[b];
    for (int i = 0; i < 32; i += 2) {
        int l[2], sarr[2], iv[2];
#pragma unroll
        for (int u = 0; u < 2; u++) {
            l[u] = (i + u) * 4 + sg;
            sarr[u] = blockIdx.x * 128 + l[u];
        }
#pragma unroll
        for (int u = 0; u < 2; u++) iv[u] = g_idx[b * NS + sarr[u]];
        float4 ea[2], eb[2];
#pragma unroll
        for (int u = 0; u < 2; u++) {
            const float4* em = (const float4*)(sp_emb + (layer * NPSP + iv[u]) * NED);
            ea[u] = em[0]; eb[u] = em[1];
        }
#pragma unroll
        for (int u = 0; u < 2; u++) {
            float spv = sb[c];
            spv += ea[u].x * sw[0 * NC + c];
            spv += ea[u].y * sw[1 * NC + c];
            spv += ea[u].z * sw[2 * NC + c];
            spv += ea[u].w * sw[3 * NC + c];
            spv += eb[u].x * sw[4 * NC + c];
            spv += eb[u].y * sw[5 * NC + c];
            spv += eb[u].z * sw[6 * NC + c];
            spv += eb[u].w * sw[7 * NC + c];
            const ulonglong2* tw2 = (const ulonglong2*)(stw + l[u] * 32);
            ull accC = 0ull, accS = 0ull;
            ulonglong2 tc0 = tw2[0], tc1 = tw2[1], tc2 = tw2[2], tc3 = tw2[3];
            ulonglong2 ts0 = tw2[4], ts1 = tw2[5], ts2 = tw2[6], ts3 = tw2[7];
            accC = f2fma(cRp[0], tc0.x, accC); accC = f2fma(cRp[1], tc0.y, accC);
            accC = f2fma(cRp[2], tc1.x, accC); accC = f2fma(cRp[3], tc1.y, accC);
            accC = f2fma(cRp[4], tc2.x, accC); accC = f2fma(cRp[5], tc2.y, accC);
            accC = f2fma(cRp[6], tc3.x, accC); accC = f2fma(cRp[7], tc3.y, accC);
            accS = f2fma(cIp[0], ts0.x, accS); accS = f2fma(cIp[1], ts0.y, accS);
            accS = f2fma(cIp[2], ts1.x, accS); accS = f2fma(cIp[3], ts1.y, accS);
            accS = f2fma(cIp[4], ts2.x, accS); accS = f2fma(cIp[5], ts2.y, accS);
            accS = f2fma(cIp[6], ts3.x, accS); accS = f2fma(cIp[7], ts3.y, accS);
            float clo, chi, slo, shi;
            f2unpack(accC, clo, chi);
            f2unpack(accS, slo, shi);
            float spec = (clo + chi) - (slo + shi);
            float v = w0 * spv + spec;
            float gl = 0.5f * v * (1.0f + erff(v * 0.70710678118654752f));
            g_h[(b * NS + sarr[u]) * NC + c] = gl;
            if (do_dft) {
                ull d = f2pack(gl, gl);
                aC[0] = f2fma(d, tc0.x, aC[0]); aC[1] = f2fma(d, tc0.y, aC[1]);
                aC[2] = f2fma(d, tc1.x, aC[2]); aC[3] = f2fma(d, tc1.y, aC[3]);
                aC[4] = f2fma(d, tc2.x, aC[4]); aC[5] = f2fma(d, tc2.y, aC[5]);
                aC[6] = f2fma(d, tc3.x, aC[6]); aC[7] = f2fma(d, tc3.y, aC[7]);
                aS[0] = f2fma(d, ts0.x, aS[0]); aS[1] = f2fma(d, ts0.y, aS[1]);
                aS[2] = f2fma(d, ts1.x, aS[2]); aS[3] = f2fma(d, ts1.y, aS[3]);
                aS[4] = f2fma(d, ts2.x, aS[4]); aS[5] = f2fma(d, ts2.y, aS[5]);
                aS[6] = f2fma(d, ts3.x, aS[6]); aS[7] = f2fma(d, ts3.y, aS[7]);
            }
        }
    }
    if (do_dft) {
        __syncthreads();
        float* xp = g_xpart + (size_t)(b * NCH + blockIdx.x) * NC * 32;
        dft_reduce_write(stw, aC, aS, t, c, sg, xp);
    }
}

// projection: out[b,0,s] = sum_c h[b,s,c] * Wp[c] + bp
__global__ void k_proj(const float* __restrict__ Wp, const float* __restrict__ bp,
                       float* __restrict__ out) {
    __shared__ float pw[NC];
    int b = blockIdx.y, t = threadIdx.x;
    if (t < NC) pw[t] = Wp[t];
    __syncthreads();
    int s = blockIdx.x * 256 + t;
    const float* hp = g_h + (b * NS + s) * NC;
    float acc = 0.f;
#pragma unroll 16
    for (int c = 0; c < NC; c++) acc += hp[c] * pw[c];
    out[b * NS + s] = acc + bp[0];
}

extern "C" void kernel_launch(void* const* d_in, const int* in_sizes, int n_in,
                              void* d_out, int out_size) {
    const float* x      = (const float*)d_in[0];
    const float* lift_W = (const float*)d_in[1];
    const float* lift_b = (const float*)d_in[2];
    const float* proj_W = (const float*)d_in[3];
    const float* proj_b = (const float*)d_in[4];
    const float* sp_emb = (const float*)d_in[5];
    const float* sp_W   = (const float*)d_in[6];
    const float* sp_b   = (const float*)d_in[7];
    const float* fr_emb = (const float*)d_in[8];
    const float* fr_W   = (const float*)d_in[9];
    const float* fr_b   = (const float*)d_in[10];
    const float* g_W1   = (const float*)d_in[11];
    const float* g_b1   = (const float*)d_in[12];
    const float* g_W2   = (const float*)d_in[13];
    const float* g_b2   = (const float*)d_in[14];
    const float* mhf_Wr = (const float*)d_in[15];
    const float* mhf_Wi = (const float*)d_in[16];
    float* out = (float*)d_out;

    k_twiddle<<<NS / 256, 256>>>();
    k_lift<<<dim3(NS / 128, NB), 256>>>(x, lift_W, lift_b);
    for (int l = 0; l < 4; l++) {
        k_scidx<<<dim3(NS / 256, NB), 256>>>(sp_emb, l);
        k_small<<<NB, 256>>>(sp_W, sp_b, fr_emb, fr_W, fr_b,
                             g_W1, g_b1, g_W2, g_b2, mhf_Wr, mhf_Wi, l);
        k_synth<<<dim3(NS / 128, NB), 256>>>(sp_emb, sp_W, sp_b, l, l < 3 ? 1 : 0);
    }
    k_proj<<<dim3(NS / 256, NB), 256>>>(proj_W, proj_b, out);
}

// round 16
// speedup vs baseline: 1.1724x; 1.1724x over previous
#include <cuda_runtime.h>
#include <cuda_bf16.h>
#include <math.h>
#include <stdint.h>

#define NB 16
#define NS 16384
#define NC 64
#define NM 16
#define NPSP 500
#define NPFR 200
#define NED 8
#define NCH 128         // DFT chunks over s (128 s each) — matches producer blocks
#define NG 8            // second-level reduction groups (16 chunks each)

typedef unsigned long long ull;

__device__ __forceinline__ ull f2pack(float lo, float hi) {
    ull r; asm("mov.b64 %0, {%1,%2};" : "=l"(r) : "f"(lo), "f"(hi)); return r;
}
__device__ __forceinline__ void f2unpack(ull v, float& lo, float& hi) {
    asm("mov.b64 {%0,%1}, %2;" : "=f"(lo), "=f"(hi) : "l"(v));
}
__device__ __forceinline__ ull f2fma(ull a, ull b, ull c) {
    ull d; asm("fma.rn.f32x2 %0, %1, %2, %3;" : "=l"(d) : "l"(a), "l"(b), "l"(c)); return d;
}

// -------- scratch (static device globals; no runtime allocation) -----------
__device__ float g_h[NB * NS * NC];                 // [b][s][c]  64 MB
__device__ float g_tw[NS * 32];                     // per s: cos[16], sin[16]
__device__ int   g_idx[NB * NS];                    // spatial engram idx
__device__ float g_xpart[NB * NCH * NC * 32];       // DFT partials (16.8 MB)
__device__ float g_xp2[NB * NG * NC * 32];          // level-2 partials (2 MB)
__device__ float g_epart[NB * 64 * NED];            // embedding partial sums
__device__ float g_cR[NB * NC * NM];                // combined mode coef (pre-scaled)
__device__ float g_cI[NB * NC * NM];
__device__ float g_w0[NB];                          // gate weight for sp branch

// ---------------------------------------------------------------------------
// fp32 twiddles with exact integer phase reduction
__global__ void k_twiddle() {
    int s = blockIdx.x * 256 + threadIdx.x;
    if (s >= NS) return;
#pragma unroll
    for (int k = 0; k < 16; k++) {
        int r = (k * s) & (NS - 1);
        float a = (float)r * (2.0f * 3.14159265358979323846f / (float)NS);
        float sv, cv; sincosf(a, &sv, &cv);
        g_tw[s * 32 + k]      = cv;
        g_tw[s * 32 + 16 + k] = sv;
    }
}

// ---- shared helper: two-pass (cos, sin) cross-group reduction + xpart write.
__device__ __forceinline__ void dft_reduce_write(float* stw16, ull* aC, ull* aS,
                                                 int t, int c, int sg,
                                                 float* xp) {
#pragma unroll
    for (int j = 0; j < 8; j++) {
        float lo, hi;
        f2unpack(aC[j], lo, hi);
        stw16[((2*j)   * 64 + c) * 4 + sg] = lo;
        stw16[((2*j+1) * 64 + c) * 4 + sg] = hi;
    }
    __syncthreads();
#pragma unroll
    for (int it = 0; it < 4; it++) {
        int p = t + it * 256;            // p = k*64 + c
        int k = p >> 6, cc = p & 63;
        const float* r = stw16 + p * 4;
        xp[cc * 32 + k] = ((r[0] + r[1]) + r[2]) + r[3];
    }
    __syncthreads();
#pragma unroll
    for (int j = 0; j < 8; j++) {
        float lo, hi;
        f2unpack(aS[j], lo, hi);
        stw16[((2*j)   * 64 + c) * 4 + sg] = lo;
        stw16[((2*j+1) * 64 + c) * 4 + sg] = hi;
    }
    __syncthreads();
#pragma unroll
    for (int it = 0; it < 4; it++) {
        int p = t + it * 256;
        int k = p >> 6, cc = p & 63;
        const float* r = stw16 + p * 4;
        xp[cc * 32 + 16 + k] = ((r[0] + r[1]) + r[2]) + r[3];
    }
}

// lifting fused with layer-0 DFT partials. Block = 128 s x all channels.
__global__ void __launch_bounds__(256, 2) k_lift(const float* __restrict__ x,
                       const float* __restrict__ W,
                       const float* __restrict__ bias) {
    __shared__ float stw[128 * 32];      // tw slice (16KB), reused for reduction
    __shared__ float lw[3 * NC], lb[NC];
    int b = blockIdx.y, chunk = blockIdx.x, t = threadIdx.x;
    {
        const float4* gtw = (const float4*)(g_tw + chunk * 128 * 32);
        float4* stw4 = (float4*)stw;
#pragma unroll
        for (int j = 0; j < 4; j++) stw4[t + j * 256] = gtw[t + j * 256];
    }
    if (t < 192) lw[t] = W[t];
    if (t < NC)  lb[t] = bias[t];
    __syncthreads();
    int c = t & 63, sg = t >> 6;
    ull aC[8], aS[8];
#pragma unroll
    for (int j = 0; j < 8; j++) { aC[j] = 0ull; aS[j] = 0ull; }
    const float* xb = x + b * 3 * NS;
    float W0 = lw[c], W1 = lw[64 + c], W2 = lw[128 + c], B0 = lb[c];
    for (int i = 0; i < 32; i++) {
        int l = i * 4 + sg;
        int s = chunk * 128 + l;
        float x0 = xb[s], x1 = xb[NS + s], x2 = xb[2 * NS + s];
        float hv = B0 + x0 * W0 + x1 * W1 + x2 * W2;
        g_h[(b * NS + s) * NC + c] = hv;
        const ulonglong2* tw2 = (const ulonglong2*)(stw + l * 32);
        ull d = f2pack(hv, hv);
#pragma unroll
        for (int q = 0; q < 4; q++) {
            ulonglong2 tc = tw2[q];
            aC[2*q]   = f2fma(d, tc.x, aC[2*q]);
            aC[2*q+1] = f2fma(d, tc.y, aC[2*q+1]);
        }
#pragma unroll
        for (int q = 0; q < 4; q++) {
            ulonglong2 ts = tw2[4 + q];
            aS[2*q]   = f2fma(d, ts.x, aS[2*q]);
            aS[2*q+1] = f2fma(d, ts.y, aS[2*q+1]);
        }
    }
    __syncthreads();
    float* xp = g_xpart + (size_t)(b * NCH + chunk) * NC * 32;
    dft_reduce_write(stw, aC, aS, t, c, sg, xp);
}

// level-2 xpart reduction: block (g, b) sums chunks [g*16, g*16+16) for all 2048 values
__global__ void k_xred() {
    int g = blockIdx.x, b = blockIdx.y, t = threadIdx.x;
    const float* src = g_xpart + ((size_t)b * NCH + g * 16) * (NC * 32);
    float* dst = g_xp2 + ((size_t)b * NG + g) * (NC * 32);
#pragma unroll
    for (int it = 0; it < 8; it++) {
        int v = t + it * 256;            // [0, 2048)
        float acc = 0.f;
#pragma unroll
        for (int ch = 0; ch < 16; ch++)
            acc += src[(size_t)ch * (NC * 32) + v];
        dst[v] = acc;
    }
}

// fused: channel sums (with 4-halo in smem) -> window hash -> idx + emb partials
__global__ void k_scidx(const float* __restrict__ sp_emb, int layer) {
    __shared__ float ssc[260];
    __shared__ float wred[8 * NED];
    int b = blockIdx.y, t = threadIdx.x;
    int base = blockIdx.x * 256;
    for (int j = t; j < 260; j += 256) {
        int s = base + j - 2;
        s = s < 0 ? 0 : (s > NS - 1 ? NS - 1 : s);
        const float4* hp = (const float4*)(g_h + (b * NS + s) * NC);
        float acc = 0.0f;
#pragma unroll
        for (int q = 0; q < 16; q++) {
            float4 v = hp[q];
            acc += v.x; acc += v.y; acc += v.z; acc += v.w;
        }
        ssc[j] = acc;
    }
    __syncthreads();
    int s = base + t;
    float w = ((ssc[t] + ssc[t + 1]) + ssc[t + 2]) + ssc[t + 3];
    int iv = (int)(w * 31.0f);
    iv = ((iv % NPSP) + NPSP) % NPSP;
    g_idx[b * NS + s] = iv;
    const float* em = sp_emb + (layer * NPSP + iv) * NED;
    float ev[NED];
#pragma unroll
    for (int e = 0; e < NED; e++) ev[e] = em[e];
#pragma unroll
    for (int off = 16; off > 0; off >>= 1) {
#pragma unroll
        for (int e = 0; e < NED; e++)
            ev[e] += __shfl_xor_sync(0xffffffffu, ev[e], off);
    }
    int wid = t >> 5, lid = t & 31;
    if (lid == 0) {
#pragma unroll
        for (int e = 0; e < NED; e++) wred[wid * NED + e] = ev[e];
    }
    __syncthreads();
    if (t < NED) {
        float acc = 0.f;
#pragma unroll
        for (int ww = 0; ww < 8; ww++) acc += wred[ww * NED + t];
        g_epart[(b * 64 + blockIdx.x) * NED + t] = acc;
    }
}

// per-b small math: X reduce (8 groups), mags+fr hash, mh einsum, fr proj, gate, coef
__global__ void k_small(const float* __restrict__ sp_W, const float* __restrict__ sp_b,
                        const float* __restrict__ fr_emb, const float* __restrict__ fr_W,
                        const float* __restrict__ fr_b,
                        const float* __restrict__ gW1, const float* __restrict__ gb1,
                        const float* __restrict__ gW2, const float* __restrict__ gb2,
                        const float* __restrict__ Wr, const float* __restrict__ Wi,
                        int layer) {
    __shared__ float sXR[1024], sXI[1024], sOR[1024], sOI[1024], sPR[1024];
    __shared__ float sMag[16], sEmb[8], sEm[8], sG[192], sH1[64], sW[3];
    __shared__ int sFidx;
    int b = blockIdx.x, t = threadIdx.x;
    const float invS = 1.0f / (float)NS;

    for (int it = 0; it < 4; it++) {
        int p = t + it * 256;            // p = c*16 + k
        int c = p >> 4, k = p & 15;
        float sc_ = 0.f, ss = 0.f;
        const float* src0 = g_xp2 + (size_t)b * NG * (NC * 32) + c * 32 + k;
#pragma unroll
        for (int g = 0; g < NG; g++) {
            const float* src = src0 + (size_t)g * (NC * 32);
            sc_ += src[0]; ss += src[16];
        }
        sXR[p] = sc_; sXI[p] = -ss;      // rfft: Im = -sum x*sin
    }
    __syncthreads();

    if (t < 16) {
        float acc = 0.f;
        for (int c = 0; c < NC; c++) {
            float xr = sXR[c * 16 + t], xi = sXI[c * 16 + t];
            acc += sqrtf(xr * xr + xi * xi);
        }
        sMag[t] = acc * (1.0f / 64.0f);
    }
    __syncthreads();
    if (t == 0) {
        int s = 0;
        for (int m = 0; m < 16; m++) s += (int)(sMag[m] * 1000.0f);
        sFidx = ((s % NPFR) + NPFR) % NPFR;
    }
    __syncthreads();
    if (t < 8) sEmb[t] = fr_emb[(layer * NPFR + sFidx) * NED + t];

    for (int it = 0; it < 4; it++) {
        int p = t + it * 256;
        int oc = p >> 4, m = p & 15;
        int hh = oc >> 4, o = oc & 15;
        float aR = 0.f, aI = 0.f;
#pragma unroll 4
        for (int i = 0; i < 16; i++) {
            float xr = sXR[(hh * 16 + i) * 16 + m];
            float xi = sXI[(hh * 16 + i) * 16 + m];
            int wi_ = (((layer * 4 + hh) * 16 + i) * 16 + o) * 16 + m;
            float wr = Wr[wi_], wim = Wi[wi_];
            aR += xr * wr - xi * wim;
            aI += xr * wim + xi * wr;
        }
        sOR[p] = aR; sOI[p] = aI;
    }
    __syncthreads();

    for (int it = 0; it < 4; it++) {
        int p = t + it * 256;
        int c = p >> 4, m = p & 15;
        float acc = fr_b[layer * 1024 + c * 16 + m];
#pragma unroll
        for (int e = 0; e < NED; e++)
            acc += sEmb[e] * fr_W[(layer * NED + e) * 1024 + c * 16 + m];
        sPR[p] = acc;
    }

    if (t < 8) {
        float acc = 0.f;
#pragma unroll 8
        for (int blk = 0; blk < 64; blk++) acc += g_epart[(b * 64 + blk) * NED + t];
        sEm[t] = acc * invS;
    }
    __syncthreads();

    if (t < 64) {
        float sm = sp_b[layer * NC + t];
#pragma unroll
        for (int e = 0; e < NED; e++) sm += sEm[e] * sp_W[(layer * NED + e) * NC + t];
        sG[t]       = sm;
        sG[64 + t]  = sOR[t * 16] * invS;
        sG[128 + t] = sPR[t * 16] * invS;
    }
    __syncthreads();
    if (t < 64) {
        float acc = gb1[layer * 64 + t];
#pragma unroll 8
        for (int i = 0; i < 192; i++) acc += sG[i] * gW1[(layer * 192 + i) * 64 + t];
        sH1[t] = fmaxf(acc, 0.0f);
    }
    __syncthreads();
    if (t < 3) {
        float acc = gb2[layer * 3 + t];
        for (int i = 0; i < 64; i++) acc += sH1[i] * gW2[(layer * 64 + i) * 3 + t];
        sW[t] = acc;
    }
    __syncthreads();
    if (t == 0) {
        float mx = fmaxf(sW[0], fmaxf(sW[1], sW[2]));
        float e0 = expf(sW[0] - mx), e1 = expf(sW[1] - mx), e2 = expf(sW[2] - mx);
        float inv = 1.0f / (e0 + e1 + e2);
        sW[0] = e0 * inv; sW[1] = e1 * inv; sW[2] = e2 * inv;
        g_w0[b] = sW[0];
    }
    __syncthreads();

    float w1 = sW[1], w2 = sW[2];
    for (int it = 0; it < 4; it++) {
        int p = t + it * 256;
        int k = p & 15;
        float scale = (k == 0) ? invS : 2.0f * invS;
        g_cR[b * 1024 + p] = (w1 * sOR[p] + w2 * sPR[p]) * scale;
        g_cI[b * 1024 + p] = (w1 * sOI[p]) * scale;
    }
}

// fused synthesis + NEXT layer's DFT partial accumulation.
__global__ void __launch_bounds__(256, 2) k_synth(const float* __restrict__ sp_emb,
                        const float* __restrict__ sp_W,
                        const float* __restrict__ sp_b, int layer, int do_dft) {
    __shared__ float stw[128 * 32];      // tw slice (16KB), reused for reduction
    __shared__ float sw[NED * NC], sb[NC];
    int b = blockIdx.y, t = threadIdx.x;
    {
        const float4* gtw = (const float4*)(g_tw + blockIdx.x * 128 * 32);
        float4* stw4 = (float4*)stw;
#pragma unroll
        for (int j = 0; j < 4; j++) stw4[t + j * 256] = gtw[t + j * 256];
    }
    for (int p = t; p < NED * NC; p += 256) sw[p] = sp_W[layer * NED * NC + p];
    if (t < NC) sb[t] = sp_b[layer * NC + t];
    __syncthreads();
    int c = t & 63, sg = t >> 6;
    ull cRp[8], cIp[8];
    {
        const ull* crp = (const ull*)(g_cR + (b * NC + c) * NM);
        const ull* cip = (const ull*)(g_cI + (b * NC + c) * NM);
#pragma unroll
        for (int j = 0; j < 8; j++) { cRp[j] = crp[j]; cIp[j] = cip[j]; }
    }
    ull aC[8], aS[8];
#pragma unroll
    for (int j = 0; j < 8; j++) { aC[j] = 0ull; aS[j] = 0ull; }
    float w0 = g_w0[b];
    for (int i = 0; i < 32; i += 2) {
        int l[2], sarr[2], iv[2];
#pragma unroll
        for (int u = 0; u < 2; u++) {
            l[u] = (i + u) * 4 + sg;
            sarr[u] = blockIdx.x * 128 + l[u];
        }
#pragma unroll
        for (int u = 0; u < 2; u++) iv[u] = g_idx[b * NS + sarr[u]];
        float4 ea[2], eb[2];
#pragma unroll
        for (int u = 0; u < 2; u++) {
            const float4* em = (const float4*)(sp_emb + (layer * NPSP + iv[u]) * NED);
            ea[u] = em[0]; eb[u] = em[1];
        }
#pragma unroll
        for (int u = 0; u < 2; u++) {
            float spv = sb[c];
            spv += ea[u].x * sw[0 * NC + c];
            spv += ea[u].y * sw[1 * NC + c];
            spv += ea[u].z * sw[2 * NC + c];
            spv += ea[u].w * sw[3 * NC + c];
            spv += eb[u].x * sw[4 * NC + c];
            spv += eb[u].y * sw[5 * NC + c];
            spv += eb[u].z * sw[6 * NC + c];
            spv += eb[u].w * sw[7 * NC + c];
            const ulonglong2* tw2 = (const ulonglong2*)(stw + l[u] * 32);
            ull accC = 0ull, accS = 0ull;
            ulonglong2 tc0 = tw2[0], tc1 = tw2[1], tc2 = tw2[2], tc3 = tw2[3];
            ulonglong2 ts0 = tw2[4], ts1 = tw2[5], ts2 = tw2[6], ts3 = tw2[7];
            accC = f2fma(cRp[0], tc0.x, accC); accC = f2fma(cRp[1], tc0.y, accC);
            accC = f2fma(cRp[2], tc1.x, accC); accC = f2fma(cRp[3], tc1.y, accC);
            accC = f2fma(cRp[4], tc2.x, accC); accC = f2fma(cRp[5], tc2.y, accC);
            accC = f2fma(cRp[6], tc3.x, accC); accC = f2fma(cRp[7], tc3.y, accC);
            accS = f2fma(cIp[0], ts0.x, accS); accS = f2fma(cIp[1], ts0.y, accS);
            accS = f2fma(cIp[2], ts1.x, accS); accS = f2fma(cIp[3], ts1.y, accS);
            accS = f2fma(cIp[4], ts2.x, accS); accS = f2fma(cIp[5], ts2.y, accS);
            accS = f2fma(cIp[6], ts3.x, accS); accS = f2fma(cIp[7], ts3.y, accS);
            float clo, chi, slo, shi;
            f2unpack(accC, clo, chi);
            f2unpack(accS, slo, shi);
            float spec = (clo + chi) - (slo + shi);
            float v = w0 * spv + spec;
            float gl = 0.5f * v * (1.0f + erff(v * 0.70710678118654752f));
            g_h[(b * NS + sarr[u]) * NC + c] = gl;
            if (do_dft) {
                ull d = f2pack(gl, gl);
                aC[0] = f2fma(d, tc0.x, aC[0]); aC[1] = f2fma(d, tc0.y, aC[1]);
                aC[2] = f2fma(d, tc1.x, aC[2]); aC[3] = f2fma(d, tc1.y, aC[3]);
                aC[4] = f2fma(d, tc2.x, aC[4]); aC[5] = f2fma(d, tc2.y, aC[5]);
                aC[6] = f2fma(d, tc3.x, aC[6]); aC[7] = f2fma(d, tc3.y, aC[7]);
                aS[0] = f2fma(d, ts0.x, aS[0]); aS[1] = f2fma(d, ts0.y, aS[1]);
                aS[2] = f2fma(d, ts1.x, aS[2]); aS[3] = f2fma(d, ts1.y, aS[3]);
                aS[4] = f2fma(d, ts2.x, aS[4]); aS[5] = f2fma(d, ts2.y, aS[5]);
                aS[6] = f2fma(d, ts3.x, aS[6]); aS[7] = f2fma(d, ts3.y, aS[7]);
            }
        }
    }
    if (do_dft) {
        __syncthreads();
        float* xp = g_xpart + (size_t)(b * NCH + blockIdx.x) * NC * 32;
        dft_reduce_write(stw, aC, aS, t, c, sg, xp);
    }
}

// projection: out[b,0,s] = sum_c h[b,s,c] * Wp[c] + bp
__global__ void k_proj(const float* __restrict__ Wp, const float* __restrict__ bp,
                       float* __restrict__ out) {
    __shared__ float pw[NC];
    int b = blockIdx.y, t = threadIdx.x;
    if (t < NC) pw[t] = Wp[t];
    __syncthreads();
    int s = blockIdx.x * 256 + t;
    const float* hp = g_h + (b * NS + s) * NC;
    float acc = 0.f;
#pragma unroll 16
    for (int c = 0; c < NC; c++) acc += hp[c] * pw[c];
    out[b * NS + s] = acc + bp[0];
}

extern "C" void kernel_launch(void* const* d_in, const int* in_sizes, int n_in,
                              void* d_out, int out_size) {
    const float* x      = (const float*)d_in[0];
    const float* lift_W = (const float*)d_in[1];
    const float* lift_b = (const float*)d_in[2];
    const float* proj_W = (const float*)d_in[3];
    const float* proj_b = (const float*)d_in[4];
    const float* sp_emb = (const float*)d_in[5];
    const float* sp_W   = (const float*)d_in[6];
    const float* sp_b   = (const float*)d_in[7];
    const float* fr_emb = (const float*)d_in[8];
    const float* fr_W   = (const float*)d_in[9];
    const float* fr_b   = (const float*)d_in[10];
    const float* g_W1   = (const float*)d_in[11];
    const float* g_b1   = (const float*)d_in[12];
    const float* g_W2   = (const float*)d_in[13];
    const float* g_b2   = (const float*)d_in[14];
    const float* mhf_Wr = (const float*)d_in[15];
    const float* mhf_Wi = (const float*)d_in[16];
    float* out = (float*)d_out;

    k_twiddle<<<NS / 256, 256>>>();
    k_lift<<<dim3(NS / 128, NB), 256>>>(x, lift_W, lift_b);
    for (int l = 0; l < 4; l++) {
        k_scidx<<<dim3(NS / 256, NB), 256>>>(sp_emb, l);
        k_xred<<<dim3(NG, NB), 256>>>();
        k_small<<<NB, 256>>>(sp_W, sp_b, fr_emb, fr_W, fr_b,
                             g_W1, g_b1, g_W2, g_b2, mhf_Wr, mhf_Wi, l);
        k_synth<<<dim3(NS / 128, NB), 256>>>(sp_emb, sp_W, sp_b, l, l < 3 ? 1 : 0);
    }
    k_proj<<<dim3(NS / 256, NB), 256>>>(proj_W, proj_b, out);
}